// round 11
// baseline (speedup 1.0000x reference)
#include <cuda_runtime.h>
#include <cstdint>

// CIN cross-network via warp-level HMMA (mma.sync m16n8k16 bf16, 3-pass
// hi/lo split). Warp = 16 rows x 64 cols. A-frags register-resident;
// W B-frags precomputed by prep_kernel into WFRAG4 (L2-resident), packed
// (BH,BL) per 16B for single-LDS.128 consumption, streamed via cp.async
// in 32 KB stages. P chained in MMA accumulator across k-steps of each m.

#define THREADS 256
#define TB 8

// smem byte offsets
#define O_X0 0         // float[4096]        16 KB
#define O_XK 16384     // float[128*64]      32 KB
#define O_WF 49152     // 2 x 32 KB W-frag stage buffers
#define SM_TOTAL 114688

// 80 chunks x 1024 uint4 (16 KB): [ci][slot][nt][lane] = {BH.x,BH.y,BL.x,BL.y}
__device__ __align__(16) uint4 WFRAG4[80 * 1024];

__device__ __forceinline__ uint32_t cvt_bf16x2(float lo, float hi) {
    uint32_t r;
    asm("cvt.rn.satfinite.bf16x2.f32 %0, %1, %2;" : "=r"(r) : "f"(hi), "f"(lo));
    return r;
}
__device__ __forceinline__ void split2(float a, float b, uint32_t& h, uint32_t& l) {
    uint32_t ua = __float_as_uint(a), ub = __float_as_uint(b);
    h = __byte_perm(ua, ub, 0x7632);
    float la = a - __uint_as_float(ua & 0xffff0000u);
    float lb = b - __uint_as_float(ub & 0xffff0000u);
    l = cvt_bf16x2(la, lb);
}
__device__ __forceinline__ void mma_zc(float d[4], const uint4& a, const uint2& b) {
    asm("mma.sync.aligned.m16n8k16.row.col.f32.bf16.bf16.f32 "
        "{%0,%1,%2,%3}, {%4,%5,%6,%7}, {%8,%9}, {%10,%11,%12,%13};"
        : "=f"(d[0]), "=f"(d[1]), "=f"(d[2]), "=f"(d[3])
        : "r"(a.x), "r"(a.y), "r"(a.z), "r"(a.w), "r"(b.x), "r"(b.y),
          "f"(0.f), "f"(0.f), "f"(0.f), "f"(0.f));
}
__device__ __forceinline__ void mma_acc(float d[4], const uint4& a, const uint2& b) {
    asm("mma.sync.aligned.m16n8k16.row.col.f32.bf16.bf16.f32 "
        "{%0,%1,%2,%3}, {%4,%5,%6,%7}, {%8,%9}, {%0,%1,%2,%3};"
        : "+f"(d[0]), "+f"(d[1]), "+f"(d[2]), "+f"(d[3])
        : "r"(a.x), "r"(a.y), "r"(a.z), "r"(a.w), "r"(b.x), "r"(b.y));
}
__device__ __forceinline__ uint32_t smem_u32(const void* p) {
    uint32_t a;
    asm("{ .reg .u64 t; cvta.to.shared.u64 t, %1; cvt.u32.u64 %0, t; }"
        : "=r"(a) : "l"(p));
    return a;
}
__device__ __forceinline__ void cp_async16(uint32_t saddr, const void* gaddr) {
    asm volatile("cp.async.cg.shared.global [%0], [%1], 16;"
                 :: "r"(saddr), "l"(gaddr) : "memory");
}
#define CP_COMMIT() asm volatile("cp.async.commit_group;" ::: "memory")
#define CP_WAIT0()  asm volatile("cp.async.wait_group 0;" ::: "memory")

// ---------- prep: split W into packed bf16 hi/lo B-fragments ----------
// ci 0..79 (L0:0-15, L1:16-47, L2:48-79)
__global__ void prep_kernel(const float* __restrict__ W0,
                            const float* __restrict__ W1,
                            const float* __restrict__ W2)
{
    int t = blockIdx.x * blockDim.x + threadIdx.x;
    if (t >= 80 * 4 * 8 * 32) return;
    int lane = t & 31;
    int ntg  = (t >> 5) & 7;
    int slot = (t >> 8) & 3;
    int ci   = t >> 10;
    const float* Wl; int c;
    if (ci < 16)      { Wl = W0; c = ci; }
    else if (ci < 48) { Wl = W1; c = ci - 16; }
    else              { Wl = W2; c = ci - 48; }
    int kk = ntg * 8 + (lane >> 2);
    int c0 = (lane & 3) * 2;
    const float* p = Wl + c * 4096 + slot * 1024 + c0 * 64 + kk;
    float a0 = p[0], a1 = p[64], a2 = p[512], a3 = p[576];
    uint2 H, L;
    split2(a0, a1, H.x, L.x);
    split2(a2, a3, H.y, L.y);
    WFRAG4[ci * 1024 + (slot * 8 + ntg) * 32 + lane] =
        make_uint4(H.x, H.y, L.x, L.y);
}

// ---------- main ----------
// build register A-frags from xk_s [r][64] for this warp's 16 rows
template<int NKS>
__device__ __forceinline__ void build_A(const float* xk_s, uint4 AH[4],
                                        uint4 AL[4], int wm, int tg, int c0)
{
#pragma unroll
    for (int ks = 0; ks < NKS; ks++) {
        const float* p = xk_s + (wm + tg) * 64 + ks * 16 + c0;
        float2 v0 = *(const float2*)(p);
        float2 v1 = *(const float2*)(p + 8 * 64);
        float2 v2 = *(const float2*)(p + 8);
        float2 v3 = *(const float2*)(p + 8 * 64 + 8);
        uint4 H, L;
        split2(v0.x, v0.y, H.x, L.x);
        split2(v1.x, v1.y, H.y, L.y);
        split2(v2.x, v2.y, H.z, L.z);
        split2(v3.x, v3.y, H.w, L.w);
        AH[ks] = H; AL[ks] = L;
    }
}

// one 32 KB stage = 8 k-slots = 8/KSM m-values (KSM = k-steps per m)
template<int KSM>
__device__ __forceinline__ void compute_stage(
    const uint4* __restrict__ WFb, const uint4 AH[4], const uint4 AL[4],
    const float* x0_s, int s, int w, int tg, int lane, float D[8][4])
{
    const int MPS = 8 / KSM;
    float xs0[MPS], xs1[MPS];
#pragma unroll
    for (int mm = 0; mm < MPS; mm++) {
        const int m = s * MPS + mm;
        xs0[mm] = x0_s[w * 512 + m * 16 + tg];
        xs1[mm] = x0_s[w * 512 + m * 16 + tg + 8];
    }
#pragma unroll
    for (int mm = 0; mm < MPS; mm++) {
        float P[8][4];
#pragma unroll
        for (int i = 0; i < KSM; i++) {
            const int si = mm * KSM + i;
            const uint4* bp = WFb + si * 256 + lane;
            uint4 Bv[4];
#pragma unroll
            for (int nt = 0; nt < 4; nt++) Bv[nt] = bp[nt * 32];
#pragma unroll
            for (int nt = 0; nt < 4; nt++) {
                uint2 BH = make_uint2(Bv[nt].x, Bv[nt].y);
                uint2 BL = make_uint2(Bv[nt].z, Bv[nt].w);
                if (i == 0) mma_zc(P[nt], AH[i], BH);
                else        mma_acc(P[nt], AH[i], BH);
                mma_acc(P[nt], AH[i], BL);
                mma_acc(P[nt], AL[i], BH);
            }
#pragma unroll
            for (int nt = 0; nt < 4; nt++) Bv[nt] = bp[(nt + 4) * 32];
#pragma unroll
            for (int nt = 0; nt < 4; nt++) {
                uint2 BH = make_uint2(Bv[nt].x, Bv[nt].y);
                uint2 BL = make_uint2(Bv[nt].z, Bv[nt].w);
                if (i == 0) mma_zc(P[nt + 4], AH[i], BH);
                else        mma_acc(P[nt + 4], AH[i], BH);
                mma_acc(P[nt + 4], AH[i], BL);
                mma_acc(P[nt + 4], AL[i], BH);
            }
        }
#pragma unroll
        for (int nt = 0; nt < 8; nt++) {
            D[nt][0] += xs0[mm] * P[nt][0];
            D[nt][1] += xs0[mm] * P[nt][1];
            D[nt][2] += xs1[mm] * P[nt][2];
            D[nt][3] += xs1[mm] * P[nt][3];
        }
    }
}

// fetch one 32 KB stage (2 consecutive 16 KB chunks) via cp.async
__device__ __forceinline__ void fetch_stage(uint32_t sdst, int ci, int tid) {
#pragma unroll
    for (int q = 0; q < 8; q++) {
        int off = (q * 256 + tid) * 16;
        cp_async16(sdst + off, (const char*)WFRAG4 + (size_t)ci * 16384 + off);
    }
    CP_COMMIT();
}

template<int KSM, bool LAST>
__device__ __forceinline__ void layer(
    int ci0, int nextci0, int L,
    float* x0_s, float* xk_s, uint4* WFs, uint32_t wf_sm,
    uint4 AH[4], uint4 AL[4],
    float* out, long long bg0,
    int tid, int lane, int wm, int w, int tg, int tc)
{
    const int NS = (KSM == 2) ? 8 : 16;   // stages this layer
    float D[8][4];
#pragma unroll
    for (int nt = 0; nt < 8; nt++)
#pragma unroll
        for (int j = 0; j < 4; j++) D[nt][j] = 0.f;

    int buf = 0;
    for (int s = 0; s < NS; s++) {
        if (s + 1 < NS) fetch_stage(wf_sm + (buf ^ 1) * 32768, ci0 + 2 * (s + 1), tid);
        else if (!LAST) fetch_stage(wf_sm + (buf ^ 1) * 32768, nextci0, tid);
        compute_stage<KSM>(WFs + buf * 2048, AH, AL, x0_s, s, w, tg, lane, D);
        CP_WAIT0();
        __syncthreads();
        buf ^= 1;
    }

    // relu -> xk_s [r][k]
    {
        int r0 = wm + tg;
#pragma unroll
        for (int nt = 0; nt < 8; nt++) {
            int cb = nt * 8 + tc * 2;
            *(float2*)&xk_s[r0 * 64 + cb] =
                make_float2(fmaxf(D[nt][0], 0.f), fmaxf(D[nt][1], 0.f));
            *(float2*)&xk_s[(r0 + 8) * 64 + cb] =
                make_float2(fmaxf(D[nt][2], 0.f), fmaxf(D[nt][3], 0.f));
        }
    }
    __syncthreads();

    // d-reduce -> out
    {
        int ob = tid >> 5, ok = (tid & 31) * 2;
        float s0 = 0.f, s1 = 0.f;
#pragma unroll
        for (int d = 0; d < 16; d++) {
            float2 v = *(const float2*)&xk_s[(ob * 16 + d) * 64 + ok];
            s0 += v.x; s1 += v.y;
        }
        *(float2*)&out[(bg0 + ob) * 192 + L * 64 + ok] = make_float2(s0, s1);
    }
    if (!LAST) {
        int c0 = tc * 2;
        build_A<4>(xk_s, AH, AL, wm, tg, c0);
    }
    __syncthreads();
}

__global__ void __launch_bounds__(THREADS, 2)
cin_kernel(const float* __restrict__ emb,
           const float* __restrict__ W0,
           const float* __restrict__ W1,
           const float* __restrict__ W2,
           float* __restrict__ out)
{
    extern __shared__ char smem[];
    float* x0_s = (float*)(smem + O_X0);
    float* xk_s = (float*)(smem + O_XK);
    uint4* WFs  = (uint4*)(smem + O_WF);
    const uint32_t wf_sm = smem_u32(smem + O_WF);

    const int tid = threadIdx.x, lane = tid & 31, w = tid >> 5;
    const int wm = w * 16;        // warp owns rows wm..wm+15, all 64 cols
    const int tg = lane >> 2, tc = lane & 3;
    const int c0 = tc * 2;
    const long long bg0 = (long long)blockIdx.x * TB;

    // load x0 (coalesced)
    {
        const float4* g = (const float4*)(emb + bg0 * 512);
        float4* sp = (float4*)x0_s;
#pragma unroll
        for (int i = 0; i < 4; i++) sp[tid + i * THREADS] = g[tid + i * THREADS];
    }
    // prefetch stage 0 (chunks 0,1)
    fetch_stage(wf_sm, 0, tid);
    __syncthreads();
    // xk_s[r][h] = x0[b][h][d], r = b*16+d (h < 32)
#pragma unroll
    for (int i = tid; i < 4096; i += THREADS) {
        int r = i >> 5, h = i & 31;
        xk_s[r * 64 + h] = x0_s[((r >> 4) << 9) + h * 16 + (r & 15)];
    }
    CP_WAIT0();
    __syncthreads();

    uint4 AH[4], AL[4];
    build_A<2>(xk_s, AH, AL, wm, tg, c0);

    layer<2, false>(0,  16, 0, x0_s, xk_s, WFs, wf_sm, AH, AL, out, bg0,
                    tid, lane, wm, w, tg, tc);
    layer<4, false>(16, 48, 1, x0_s, xk_s, WFs, wf_sm, AH, AL, out, bg0,
                    tid, lane, wm, w, tg, tc);
    layer<4, true >(48, 0,  2, x0_s, xk_s, WFs, wf_sm, AH, AL, out, bg0,
                    tid, lane, wm, w, tg, tc);
}

extern "C" void kernel_launch(void* const* d_in, const int* in_sizes, int n_in,
                              void* d_out, int out_size)
{
    const float* emb = (const float*)d_in[0];
    const float* W0  = (const float*)d_in[1];
    const float* W1  = (const float*)d_in[2];
    const float* W2  = (const float*)d_in[3];
    float* out = (float*)d_out;

    prep_kernel<<<320, 256>>>(W0, W1, W2);
    cudaFuncSetAttribute(cin_kernel,
                         cudaFuncAttributeMaxDynamicSharedMemorySize, SM_TOTAL);
    cin_kernel<<<16384 / TB, THREADS, SM_TOTAL>>>(emb, W0, W1, W2, out);
}

// round 12
// speedup vs baseline: 1.4540x; 1.4540x over previous
#include <cuda_runtime.h>
#include <cuda_fp16.h>
#include <cstdint>

// CIN cross-network via warp-level HMMA, fp16 2-pass split:
//   a = ha + la (fp16 hi + fp16 residual), W single-rounded fp16 hb
//   P = ha*hb + la*hb = a*hb  (only error: W rounding ~2^-12)
// Warp = 16 rows x 64 cols. A-frags register-resident; W fp16 B-frags
// precomputed by prep_kernel into WFRAG2, streamed via cp.async in
// 32 KB stages (4 chunks, 16 k-slots), 20 barriers total.

#define THREADS 256
#define TB 8

// smem byte offsets
#define O_X0 0         // float[4096]        16 KB
#define O_XK 16384     // float[128*64]      32 KB
#define O_WF 49152     // 2 x 32 KB W-frag stage buffers
#define SM_TOTAL 114688

// 80 chunks x 1024 uint2 (8 KB): [ci][slot][nt][lane] = fp16x2 pair of W
__device__ __align__(16) uint2 WFRAG2[80 * 1024];

__device__ __forceinline__ uint32_t pack_h2(float lo, float hi) {
    uint32_t r;
    asm("cvt.rn.f16x2.f32 %0, %1, %2;" : "=r"(r) : "f"(hi), "f"(lo));
    return r;
}
// fp16 hi + fp16 residual split of two floats (a -> low half, b -> high)
__device__ __forceinline__ void split2h(float a, float b, uint32_t& h, uint32_t& l) {
    h = pack_h2(a, b);
    __half2 hh = *reinterpret_cast<__half2*>(&h);
    l = pack_h2(a - __low2float(hh), b - __high2float(hh));
}
__device__ __forceinline__ void mma_zc(float d[4], const uint4& a, const uint2& b) {
    asm("mma.sync.aligned.m16n8k16.row.col.f32.f16.f16.f32 "
        "{%0,%1,%2,%3}, {%4,%5,%6,%7}, {%8,%9}, {%10,%11,%12,%13};"
        : "=f"(d[0]), "=f"(d[1]), "=f"(d[2]), "=f"(d[3])
        : "r"(a.x), "r"(a.y), "r"(a.z), "r"(a.w), "r"(b.x), "r"(b.y),
          "f"(0.f), "f"(0.f), "f"(0.f), "f"(0.f));
}
__device__ __forceinline__ void mma_acc(float d[4], const uint4& a, const uint2& b) {
    asm("mma.sync.aligned.m16n8k16.row.col.f32.f16.f16.f32 "
        "{%0,%1,%2,%3}, {%4,%5,%6,%7}, {%8,%9}, {%0,%1,%2,%3};"
        : "+f"(d[0]), "+f"(d[1]), "+f"(d[2]), "+f"(d[3])
        : "r"(a.x), "r"(a.y), "r"(a.z), "r"(a.w), "r"(b.x), "r"(b.y));
}
__device__ __forceinline__ uint32_t smem_u32(const void* p) {
    uint32_t a;
    asm("{ .reg .u64 t; cvta.to.shared.u64 t, %1; cvt.u32.u64 %0, t; }"
        : "=r"(a) : "l"(p));
    return a;
}
__device__ __forceinline__ void cp_async16(uint32_t saddr, const void* gaddr) {
    asm volatile("cp.async.cg.shared.global [%0], [%1], 16;"
                 :: "r"(saddr), "l"(gaddr) : "memory");
}
#define CP_COMMIT() asm volatile("cp.async.commit_group;" ::: "memory")
#define CP_WAIT0()  asm volatile("cp.async.wait_group 0;" ::: "memory")

// ---------- prep: convert W to fp16 B-fragments ----------
// ci 0..79 (L0:0-15, L1:16-47, L2:48-79)
__global__ void prep_kernel(const float* __restrict__ W0,
                            const float* __restrict__ W1,
                            const float* __restrict__ W2)
{
    int t = blockIdx.x * blockDim.x + threadIdx.x;
    if (t >= 80 * 4 * 8 * 32) return;
    int lane = t & 31;
    int ntg  = (t >> 5) & 7;
    int slot = (t >> 8) & 3;
    int ci   = t >> 10;
    const float* Wl; int c;
    if (ci < 16)      { Wl = W0; c = ci; }
    else if (ci < 48) { Wl = W1; c = ci - 16; }
    else              { Wl = W2; c = ci - 48; }
    int kk = ntg * 8 + (lane >> 2);
    int c0 = (lane & 3) * 2;
    const float* p = Wl + c * 4096 + slot * 1024 + c0 * 64 + kk;
    WFRAG2[ci * 1024 + (slot * 8 + ntg) * 32 + lane] =
        make_uint2(pack_h2(p[0], p[64]), pack_h2(p[512], p[576]));
}

// ---------- main ----------
// build register A-frags (fp16 hi/lo) from xk_s [r][64], this warp's 16 rows
template<int NKS>
__device__ __forceinline__ void build_A(const float* xk_s, uint4 AH[4],
                                        uint4 AL[4], int wm, int tg, int c0)
{
#pragma unroll
    for (int ks = 0; ks < NKS; ks++) {
        const float* p = xk_s + (wm + tg) * 64 + ks * 16 + c0;
        float2 v0 = *(const float2*)(p);
        float2 v1 = *(const float2*)(p + 8 * 64);
        float2 v2 = *(const float2*)(p + 8);
        float2 v3 = *(const float2*)(p + 8 * 64 + 8);
        uint4 H, L;
        split2h(v0.x, v0.y, H.x, L.x);
        split2h(v1.x, v1.y, H.y, L.y);
        split2h(v2.x, v2.y, H.z, L.z);
        split2h(v3.x, v3.y, H.w, L.w);
        AH[ks] = H; AL[ks] = L;
    }
}

// one 32 KB stage = 16 k-slots = 16/KSM m-values (KSM = k-steps per m)
template<int KSM>
__device__ __forceinline__ void compute_stage(
    const uint2* __restrict__ WFb, const uint4 AH[4], const uint4 AL[4],
    const float* x0_s, int s, int w, int tg, int lane, float D[8][4])
{
    const int MPS = 16 / KSM;
#pragma unroll
    for (int mm = 0; mm < MPS; mm++) {
        const int m = s * MPS + mm;
        float xs0 = x0_s[w * 512 + m * 16 + tg];
        float xs1 = x0_s[w * 512 + m * 16 + tg + 8];
        float P[8][4];
#pragma unroll
        for (int i = 0; i < KSM; i++) {
            const int si = mm * KSM + i;
            const uint2* bp = WFb + si * 256 + lane;
            uint2 Bv[8];
#pragma unroll
            for (int nt = 0; nt < 8; nt++) Bv[nt] = bp[nt * 32];
#pragma unroll
            for (int nt = 0; nt < 8; nt++) {
                if (i == 0) mma_zc(P[nt], AH[i], Bv[nt]);
                else        mma_acc(P[nt], AH[i], Bv[nt]);
                mma_acc(P[nt], AL[i], Bv[nt]);
            }
        }
#pragma unroll
        for (int nt = 0; nt < 8; nt++) {
            D[nt][0] += xs0 * P[nt][0];
            D[nt][1] += xs0 * P[nt][1];
            D[nt][2] += xs1 * P[nt][2];
            D[nt][3] += xs1 * P[nt][3];
        }
    }
}

// fetch one 32 KB stage (4 consecutive 8 KB chunks) via cp.async
__device__ __forceinline__ void fetch_stage(uint32_t sdst, int ci, int tid) {
#pragma unroll
    for (int q = 0; q < 8; q++) {
        int off = (q * 256 + tid) * 16;
        cp_async16(sdst + off, (const char*)WFRAG2 + (size_t)ci * 8192 + off);
    }
    CP_COMMIT();
}

template<int KSM, bool LAST>
__device__ __forceinline__ void layer(
    int ci0, int nextci0, int L,
    float* x0_s, float* xk_s, uint2* WFs, uint32_t wf_sm,
    uint4 AH[4], uint4 AL[4],
    float* out, long long bg0,
    int tid, int lane, int wm, int w, int tg, int tc)
{
    const int NS = (KSM == 2) ? 4 : 8;   // stages this layer
    float D[8][4];
#pragma unroll
    for (int nt = 0; nt < 8; nt++)
#pragma unroll
        for (int j = 0; j < 4; j++) D[nt][j] = 0.f;

    int buf = 0;
    for (int s = 0; s < NS; s++) {
        if (s + 1 < NS) fetch_stage(wf_sm + (buf ^ 1) * 32768, ci0 + 4 * (s + 1), tid);
        else if (!LAST) fetch_stage(wf_sm + (buf ^ 1) * 32768, nextci0, tid);
        compute_stage<KSM>(WFs + buf * 4096, AH, AL, x0_s, s, w, tg, lane, D);
        CP_WAIT0();
        __syncthreads();
        buf ^= 1;
    }

    // relu -> xk_s [r][k]
    {
        int r0 = wm + tg;
#pragma unroll
        for (int nt = 0; nt < 8; nt++) {
            int cb = nt * 8 + tc * 2;
            *(float2*)&xk_s[r0 * 64 + cb] =
                make_float2(fmaxf(D[nt][0], 0.f), fmaxf(D[nt][1], 0.f));
            *(float2*)&xk_s[(r0 + 8) * 64 + cb] =
                make_float2(fmaxf(D[nt][2], 0.f), fmaxf(D[nt][3], 0.f));
        }
    }
    __syncthreads();

    // d-reduce -> out
    {
        int ob = tid >> 5, ok = (tid & 31) * 2;
        float s0 = 0.f, s1 = 0.f;
#pragma unroll
        for (int d = 0; d < 16; d++) {
            float2 v = *(const float2*)&xk_s[(ob * 16 + d) * 64 + ok];
            s0 += v.x; s1 += v.y;
        }
        *(float2*)&out[(bg0 + ob) * 192 + L * 64 + ok] = make_float2(s0, s1);
    }
    if (!LAST) {
        int c0 = tc * 2;
        build_A<4>(xk_s, AH, AL, wm, tg, c0);
    }
    __syncthreads();
}

__global__ void __launch_bounds__(THREADS, 2)
cin_kernel(const float* __restrict__ emb,
           const float* __restrict__ W0,
           const float* __restrict__ W1,
           const float* __restrict__ W2,
           float* __restrict__ out)
{
    extern __shared__ char smem[];
    float* x0_s = (float*)(smem + O_X0);
    float* xk_s = (float*)(smem + O_XK);
    uint2* WFs  = (uint2*)(smem + O_WF);
    const uint32_t wf_sm = smem_u32(smem + O_WF);

    const int tid = threadIdx.x, lane = tid & 31, w = tid >> 5;
    const int wm = w * 16;        // warp owns rows wm..wm+15, all 64 cols
    const int tg = lane >> 2, tc = lane & 3;
    const int c0 = tc * 2;
    const long long bg0 = (long long)blockIdx.x * TB;

    // load x0 (coalesced)
    {
        const float4* g = (const float4*)(emb + bg0 * 512);
        float4* sp = (float4*)x0_s;
#pragma unroll
        for (int i = 0; i < 4; i++) sp[tid + i * THREADS] = g[tid + i * THREADS];
    }
    // prefetch stage 0 (chunks 0..3)
    fetch_stage(wf_sm, 0, tid);
    __syncthreads();
    // xk_s[r][h] = x0[b][h][d], r = b*16+d (h < 32)
#pragma unroll
    for (int i = tid; i < 4096; i += THREADS) {
        int r = i >> 5, h = i & 31;
        xk_s[r * 64 + h] = x0_s[((r >> 4) << 9) + h * 16 + (r & 15)];
    }
    CP_WAIT0();
    __syncthreads();

    uint4 AH[4], AL[4];
    build_A<2>(xk_s, AH, AL, wm, tg, c0);

    layer<2, false>(0,  16, 0, x0_s, xk_s, WFs, wf_sm, AH, AL, out, bg0,
                    tid, lane, wm, w, tg, tc);
    layer<4, false>(16, 48, 1, x0_s, xk_s, WFs, wf_sm, AH, AL, out, bg0,
                    tid, lane, wm, w, tg, tc);
    layer<4, true >(48, 0,  2, x0_s, xk_s, WFs, wf_sm, AH, AL, out, bg0,
                    tid, lane, wm, w, tg, tc);
}

extern "C" void kernel_launch(void* const* d_in, const int* in_sizes, int n_in,
                              void* d_out, int out_size)
{
    const float* emb = (const float*)d_in[0];
    const float* W0  = (const float*)d_in[1];
    const float* W1  = (const float*)d_in[2];
    const float* W2  = (const float*)d_in[3];
    float* out = (float*)d_out;

    prep_kernel<<<320, 256>>>(W0, W1, W2);
    cudaFuncSetAttribute(cin_kernel,
                         cudaFuncAttributeMaxDynamicSharedMemorySize, SM_TOTAL);
    cin_kernel<<<16384 / TB, THREADS, SM_TOTAL>>>(emb, W0, W1, W2, out);
}

// round 13
// speedup vs baseline: 2.4631x; 1.6941x over previous
#include <cuda_runtime.h>
#include <cuda_fp16.h>
#include <cstdint>

// CIN cross-network via warp-level HMMA, single-pass fp16 (both A and W
// single-rounded to fp16; fp32 accumulate). Warp tile = 32 rows x 32 cols
// (2 row-groups x 4 n-tiles), 4 row-warps x 2 col-warps.
// A-frags register-resident; W fp16 B-frags precomputed by prep_kernel
// into WFRAG2 and streamed via cp.async in 32 KB stages (16 k-slots).
// P chained in MMA accumulator across k-steps of each m; fold per m.

#define THREADS 256
#define TB 8

// smem byte offsets
#define O_X0 0         // float[4096]        16 KB
#define O_XK 16384     // float[128*64]      32 KB
#define O_WF 49152     // 2 x 32 KB W-frag stage buffers
#define SM_TOTAL 114688

// 80 chunks x 1024 uint2 (8 KB): [ci][slot][nt][lane] = fp16x2 pair of W
__device__ __align__(16) uint2 WFRAG2[80 * 1024];

__device__ __forceinline__ uint32_t pack_h2(float lo, float hi) {
    uint32_t r;
    asm("cvt.rn.f16x2.f32 %0, %1, %2;" : "=r"(r) : "f"(hi), "f"(lo));
    return r;
}
__device__ __forceinline__ void mma_zc(float d[4], const uint4& a, const uint2& b) {
    asm("mma.sync.aligned.m16n8k16.row.col.f32.f16.f16.f32 "
        "{%0,%1,%2,%3}, {%4,%5,%6,%7}, {%8,%9}, {%10,%11,%12,%13};"
        : "=f"(d[0]), "=f"(d[1]), "=f"(d[2]), "=f"(d[3])
        : "r"(a.x), "r"(a.y), "r"(a.z), "r"(a.w), "r"(b.x), "r"(b.y),
          "f"(0.f), "f"(0.f), "f"(0.f), "f"(0.f));
}
__device__ __forceinline__ void mma_acc(float d[4], const uint4& a, const uint2& b) {
    asm("mma.sync.aligned.m16n8k16.row.col.f32.f16.f16.f32 "
        "{%0,%1,%2,%3}, {%4,%5,%6,%7}, {%8,%9}, {%0,%1,%2,%3};"
        : "+f"(d[0]), "+f"(d[1]), "+f"(d[2]), "+f"(d[3])
        : "r"(a.x), "r"(a.y), "r"(a.z), "r"(a.w), "r"(b.x), "r"(b.y));
}
__device__ __forceinline__ uint32_t smem_u32(const void* p) {
    uint32_t a;
    asm("{ .reg .u64 t; cvta.to.shared.u64 t, %1; cvt.u32.u64 %0, t; }"
        : "=r"(a) : "l"(p));
    return a;
}
__device__ __forceinline__ void cp_async16(uint32_t saddr, const void* gaddr) {
    asm volatile("cp.async.cg.shared.global [%0], [%1], 16;"
                 :: "r"(saddr), "l"(gaddr) : "memory");
}
#define CP_COMMIT() asm volatile("cp.async.commit_group;" ::: "memory")
#define CP_WAIT0()  asm volatile("cp.async.wait_group 0;" ::: "memory")

// ---------- prep: convert W to fp16 B-fragments ----------
// ci 0..79 (L0:0-15, L1:16-47, L2:48-79)
__global__ void prep_kernel(const float* __restrict__ W0,
                            const float* __restrict__ W1,
                            const float* __restrict__ W2)
{
    int t = blockIdx.x * blockDim.x + threadIdx.x;
    if (t >= 80 * 4 * 8 * 32) return;
    int lane = t & 31;
    int ntg  = (t >> 5) & 7;
    int slot = (t >> 8) & 3;
    int ci   = t >> 10;
    const float* Wl; int c;
    if (ci < 16)      { Wl = W0; c = ci; }
    else if (ci < 48) { Wl = W1; c = ci - 16; }
    else              { Wl = W2; c = ci - 48; }
    int kk = ntg * 8 + (lane >> 2);
    int c0 = (lane & 3) * 2;
    const float* p = Wl + c * 4096 + slot * 1024 + c0 * 64 + kk;
    WFRAG2[ci * 1024 + (slot * 8 + ntg) * 32 + lane] =
        make_uint2(pack_h2(p[0], p[64]), pack_h2(p[512], p[576]));
}

// ---------- main ----------
// build register A-frags (fp16) from xk_s [r][64], 2 row-groups of 16 rows
template<int NKS>
__device__ __forceinline__ void build_A(const float* xk_s, uint4 AH[2][4],
                                        int wr, int tg, int c0)
{
#pragma unroll
    for (int rg = 0; rg < 2; rg++)
#pragma unroll
        for (int ks = 0; ks < NKS; ks++) {
            const float* p = xk_s + (wr * 32 + rg * 16 + tg) * 64 + ks * 16 + c0;
            float2 v0 = *(const float2*)(p);
            float2 v1 = *(const float2*)(p + 8 * 64);
            float2 v2 = *(const float2*)(p + 8);
            float2 v3 = *(const float2*)(p + 8 * 64 + 8);
            AH[rg][ks] = make_uint4(pack_h2(v0.x, v0.y), pack_h2(v1.x, v1.y),
                                    pack_h2(v2.x, v2.y), pack_h2(v3.x, v3.y));
        }
}

// one 32 KB stage = 16 k-slots = 16/KSM m-values (KSM = k-steps per m)
template<int KSM>
__device__ __forceinline__ void compute_stage(
    const uint2* __restrict__ WFb, const uint4 AH[2][4],
    const float* x0_s, int s, int wr, int wc, int tg, int lane, float D[2][4][4])
{
    const int MPS = 16 / KSM;
#pragma unroll
    for (int mm = 0; mm < MPS; mm++) {
        const int m = s * MPS + mm;
        float xs[2][2];
#pragma unroll
        for (int rg = 0; rg < 2; rg++) {
            xs[rg][0] = x0_s[(wr * 2 + rg) * 512 + m * 16 + tg];
            xs[rg][1] = x0_s[(wr * 2 + rg) * 512 + m * 16 + tg + 8];
        }
        float P[2][4][4];
#pragma unroll
        for (int i = 0; i < KSM; i++) {
            const int si = mm * KSM + i;
            const uint2* bp = WFb + si * 256 + wc * 128 + lane;
            uint2 Bv[4];
#pragma unroll
            for (int nt = 0; nt < 4; nt++) Bv[nt] = bp[nt * 32];
#pragma unroll
            for (int rg = 0; rg < 2; rg++)
#pragma unroll
                for (int nt = 0; nt < 4; nt++) {
                    if (i == 0) mma_zc(P[rg][nt], AH[rg][i], Bv[nt]);
                    else        mma_acc(P[rg][nt], AH[rg][i], Bv[nt]);
                }
        }
#pragma unroll
        for (int rg = 0; rg < 2; rg++)
#pragma unroll
            for (int nt = 0; nt < 4; nt++) {
                D[rg][nt][0] += xs[rg][0] * P[rg][nt][0];
                D[rg][nt][1] += xs[rg][0] * P[rg][nt][1];
                D[rg][nt][2] += xs[rg][1] * P[rg][nt][2];
                D[rg][nt][3] += xs[rg][1] * P[rg][nt][3];
            }
    }
}

// fetch one 32 KB stage (4 consecutive 8 KB chunks) via cp.async
__device__ __forceinline__ void fetch_stage(uint32_t sdst, int ci, int tid) {
#pragma unroll
    for (int q = 0; q < 8; q++) {
        int off = (q * 256 + tid) * 16;
        cp_async16(sdst + off, (const char*)WFRAG2 + (size_t)ci * 8192 + off);
    }
    CP_COMMIT();
}

template<int KSM, bool LAST>
__device__ __forceinline__ void layer(
    int ci0, int nextci0, int L,
    float* x0_s, float* xk_s, uint2* WFs, uint32_t wf_sm,
    uint4 AH[2][4],
    float* out, long long bg0,
    int tid, int lane, int wr, int wc, int tg, int tc)
{
    const int NS = (KSM == 2) ? 4 : 8;   // stages this layer
    float D[2][4][4];
#pragma unroll
    for (int rg = 0; rg < 2; rg++)
#pragma unroll
        for (int nt = 0; nt < 4; nt++)
#pragma unroll
            for (int j = 0; j < 4; j++) D[rg][nt][j] = 0.f;

    int buf = 0;
    for (int s = 0; s < NS; s++) {
        if (s + 1 < NS) fetch_stage(wf_sm + (buf ^ 1) * 32768, ci0 + 4 * (s + 1), tid);
        else if (!LAST) fetch_stage(wf_sm + (buf ^ 1) * 32768, nextci0, tid);
        compute_stage<KSM>(WFs + buf * 4096, AH, x0_s, s, wr, wc, tg, lane, D);
        CP_WAIT0();
        __syncthreads();
        buf ^= 1;
    }

    // relu -> xk_s [r][k]
#pragma unroll
    for (int rg = 0; rg < 2; rg++) {
        int r0 = wr * 32 + rg * 16 + tg;
#pragma unroll
        for (int nt = 0; nt < 4; nt++) {
            int cb = wc * 32 + nt * 8 + tc * 2;
            *(float2*)&xk_s[r0 * 64 + cb] =
                make_float2(fmaxf(D[rg][nt][0], 0.f), fmaxf(D[rg][nt][1], 0.f));
            *(float2*)&xk_s[(r0 + 8) * 64 + cb] =
                make_float2(fmaxf(D[rg][nt][2], 0.f), fmaxf(D[rg][nt][3], 0.f));
        }
    }
    __syncthreads();

    // d-reduce -> out
    {
        int ob = tid >> 5, ok = (tid & 31) * 2;
        float s0 = 0.f, s1 = 0.f;
#pragma unroll
        for (int d = 0; d < 16; d++) {
            float2 v = *(const float2*)&xk_s[(ob * 16 + d) * 64 + ok];
            s0 += v.x; s1 += v.y;
        }
        *(float2*)&out[(bg0 + ob) * 192 + L * 64 + ok] = make_float2(s0, s1);
    }
    if (!LAST) {
        int c0 = tc * 2;
        build_A<4>(xk_s, AH, wr, tg, c0);
    }
    __syncthreads();
}

__global__ void __launch_bounds__(THREADS, 2)
cin_kernel(const float* __restrict__ emb,
           const float* __restrict__ W0,
           const float* __restrict__ W1,
           const float* __restrict__ W2,
           float* __restrict__ out)
{
    extern __shared__ char smem[];
    float* x0_s = (float*)(smem + O_X0);
    float* xk_s = (float*)(smem + O_XK);
    uint2* WFs  = (uint2*)(smem + O_WF);
    const uint32_t wf_sm = smem_u32(smem + O_WF);

    const int tid = threadIdx.x, lane = tid & 31, w = tid >> 5;
    const int wr = w & 3;         // row-warp: rows 32*wr .. 32*wr+31
    const int wc = w >> 2;        // col-warp: cols 32*wc .. 32*wc+31
    const int tg = lane >> 2, tc = lane & 3;
    const int c0 = tc * 2;
    const long long bg0 = (long long)blockIdx.x * TB;

    // load x0 (coalesced)
    {
        const float4* g = (const float4*)(emb + bg0 * 512);
        float4* sp = (float4*)x0_s;
#pragma unroll
        for (int i = 0; i < 4; i++) sp[tid + i * THREADS] = g[tid + i * THREADS];
    }
    // prefetch stage 0 (chunks 0..3)
    fetch_stage(wf_sm, 0, tid);
    __syncthreads();
    // xk_s[r][h] = x0[b][h][d], r = b*16+d (h < 32)
#pragma unroll
    for (int i = tid; i < 4096; i += THREADS) {
        int r = i >> 5, h = i & 31;
        xk_s[r * 64 + h] = x0_s[((r >> 4) << 9) + h * 16 + (r & 15)];
    }
    CP_WAIT0();
    __syncthreads();

    uint4 AH[2][4];
    build_A<2>(xk_s, AH, wr, tg, c0);

    layer<2, false>(0,  16, 0, x0_s, xk_s, WFs, wf_sm, AH, out, bg0,
                    tid, lane, wr, wc, tg, tc);
    layer<4, false>(16, 48, 1, x0_s, xk_s, WFs, wf_sm, AH, out, bg0,
                    tid, lane, wr, wc, tg, tc);
    layer<4, true >(48, 0,  2, x0_s, xk_s, WFs, wf_sm, AH, out, bg0,
                    tid, lane, wr, wc, tg, tc);
}

extern "C" void kernel_launch(void* const* d_in, const int* in_sizes, int n_in,
                              void* d_out, int out_size)
{
    const float* emb = (const float*)d_in[0];
    const float* W0  = (const float*)d_in[1];
    const float* W1  = (const float*)d_in[2];
    const float* W2  = (const float*)d_in[3];
    float* out = (float*)d_out;

    prep_kernel<<<320, 256>>>(W0, W1, W2);
    cudaFuncSetAttribute(cin_kernel,
                         cudaFuncAttributeMaxDynamicSharedMemorySize, SM_TOTAL);
    cin_kernel<<<16384 / TB, THREADS, SM_TOTAL>>>(emb, W0, W1, W2, out);
}

// round 14
// speedup vs baseline: 2.4729x; 1.0040x over previous
#include <cuda_runtime.h>
#include <cuda_fp16.h>
#include <cstdint>

// CIN cross-network via warp-level HMMA, single-pass fp16 with x0 folded
// into the A operand: zf = hmul2(xk_frag, dup(x0)); D[128x64] is the MMA
// accumulator chained across ALL k-steps of a layer (no P, no fp32 fold).
// Warp tile = 32 rows x 32 cols. W fp16 B-frags precomputed by prep_kernel,
// streamed via cp.async in 32 KB stages (16 k-slots), 20 barriers total.

#define THREADS 256
#define TB 8

// smem byte offsets (x0h is built in-place over the fp32 x0 staging area)
#define O_X0 0         // fp32 x0 [4096] -> then uint32 x0h[128][32]  16 KB
#define O_XK 16384     // float[128*64]      32 KB
#define O_WF 49152     // 2 x 32 KB W-frag stage buffers
#define SM_TOTAL 114688

// 80 chunks x 1024 uint2 (8 KB): [ci][slot][nt][lane] = fp16x2 pair of W
__device__ __align__(16) uint2 WFRAG2[80 * 1024];

__device__ __forceinline__ uint32_t pack_h2(float lo, float hi) {
    uint32_t r;
    asm("cvt.rn.f16x2.f32 %0, %1, %2;" : "=r"(r) : "f"(hi), "f"(lo));
    return r;
}
__device__ __forceinline__ uint32_t hmul2(uint32_t a, uint32_t b) {
    uint32_t r;
    asm("mul.rn.f16x2 %0, %1, %2;" : "=r"(r) : "r"(a), "r"(b));
    return r;
}
__device__ __forceinline__ void mma_acc(float d[4], const uint4& a, const uint2& b) {
    asm("mma.sync.aligned.m16n8k16.row.col.f32.f16.f16.f32 "
        "{%0,%1,%2,%3}, {%4,%5,%6,%7}, {%8,%9}, {%0,%1,%2,%3};"
        : "+f"(d[0]), "+f"(d[1]), "+f"(d[2]), "+f"(d[3])
        : "r"(a.x), "r"(a.y), "r"(a.z), "r"(a.w), "r"(b.x), "r"(b.y));
}
__device__ __forceinline__ uint32_t smem_u32(const void* p) {
    uint32_t a;
    asm("{ .reg .u64 t; cvta.to.shared.u64 t, %1; cvt.u32.u64 %0, t; }"
        : "=r"(a) : "l"(p));
    return a;
}
__device__ __forceinline__ void cp_async16(uint32_t saddr, const void* gaddr) {
    asm volatile("cp.async.cg.shared.global [%0], [%1], 16;"
                 :: "r"(saddr), "l"(gaddr) : "memory");
}
#define CP_COMMIT() asm volatile("cp.async.commit_group;" ::: "memory")
#define CP_WAIT0()  asm volatile("cp.async.wait_group 0;" ::: "memory")

// ---------- prep: convert W to fp16 B-fragments ----------
// ci 0..79 (L0:0-15, L1:16-47, L2:48-79)
__global__ void prep_kernel(const float* __restrict__ W0,
                            const float* __restrict__ W1,
                            const float* __restrict__ W2)
{
    int t = blockIdx.x * blockDim.x + threadIdx.x;
    if (t >= 80 * 4 * 8 * 32) return;
    int lane = t & 31;
    int ntg  = (t >> 5) & 7;
    int slot = (t >> 8) & 3;
    int ci   = t >> 10;
    const float* Wl; int c;
    if (ci < 16)      { Wl = W0; c = ci; }
    else if (ci < 48) { Wl = W1; c = ci - 16; }
    else              { Wl = W2; c = ci - 48; }
    int kk = ntg * 8 + (lane >> 2);
    int c0 = (lane & 3) * 2;
    const float* p = Wl + c * 4096 + slot * 1024 + c0 * 64 + kk;
    WFRAG2[ci * 1024 + (slot * 8 + ntg) * 32 + lane] =
        make_uint2(pack_h2(p[0], p[64]), pack_h2(p[512], p[576]));
}

// ---------- main ----------
// build register A-frags (fp16 xk) from xk_s [r][64], 2 row-groups x NKS ksteps
template<int NKS>
__device__ __forceinline__ void build_A(const float* xk_s, uint4 AH[2][4],
                                        int wr, int tg, int c0)
{
#pragma unroll
    for (int rg = 0; rg < 2; rg++)
#pragma unroll
        for (int ks = 0; ks < NKS; ks++) {
            const float* p = xk_s + (wr * 32 + rg * 16 + tg) * 64 + ks * 16 + c0;
            float2 v0 = *(const float2*)(p);
            float2 v1 = *(const float2*)(p + 8 * 64);
            float2 v2 = *(const float2*)(p + 8);
            float2 v3 = *(const float2*)(p + 8 * 64 + 8);
            AH[rg][ks] = make_uint4(pack_h2(v0.x, v0.y), pack_h2(v1.x, v1.y),
                                    pack_h2(v2.x, v2.y), pack_h2(v3.x, v3.y));
        }
}

// one 32 KB stage = 16 k-slots = 16/KSM m-values (KSM = k-steps per m)
template<int KSM>
__device__ __forceinline__ void compute_stage(
    const uint2* __restrict__ WFb, const uint4 AH[2][4],
    const uint32_t* __restrict__ x0h, int s, int wr, int wc, int tg, int lane,
    float D[2][4][4])
{
    const int MPS = 16 / KSM;
#pragma unroll
    for (int mm = 0; mm < MPS; mm++) {
        const int m = s * MPS + mm;
        uint32_t s0[2], s1[2];
#pragma unroll
        for (int rg = 0; rg < 2; rg++) {
            int r0 = wr * 32 + rg * 16 + tg;
            s0[rg] = x0h[r0 * 32 + m];
            s1[rg] = x0h[(r0 + 8) * 32 + m];
        }
#pragma unroll
        for (int i = 0; i < KSM; i++) {
            const int si = mm * KSM + i;
            const uint2* bp = WFb + si * 256 + wc * 128 + lane;
            uint2 Bv[4];
#pragma unroll
            for (int nt = 0; nt < 4; nt++) Bv[nt] = bp[nt * 32];
#pragma unroll
            for (int rg = 0; rg < 2; rg++) {
                uint4 zf;
                zf.x = hmul2(AH[rg][i].x, s0[rg]);
                zf.y = hmul2(AH[rg][i].y, s1[rg]);
                zf.z = hmul2(AH[rg][i].z, s0[rg]);
                zf.w = hmul2(AH[rg][i].w, s1[rg]);
#pragma unroll
                for (int nt = 0; nt < 4; nt++)
                    mma_acc(D[rg][nt], zf, Bv[nt]);
            }
        }
    }
}

// fetch one 32 KB stage (4 consecutive 8 KB chunks) via cp.async
__device__ __forceinline__ void fetch_stage(uint32_t sdst, int ci, int tid) {
#pragma unroll
    for (int q = 0; q < 8; q++) {
        int off = (q * 256 + tid) * 16;
        cp_async16(sdst + off, (const char*)WFRAG2 + (size_t)ci * 8192 + off);
    }
    CP_COMMIT();
}

template<int KSM, bool LAST>
__device__ __forceinline__ void layer(
    int ci0, int nextci0, int L,
    const uint32_t* x0h, float* xk_s, uint2* WFs, uint32_t wf_sm,
    uint4 AH[2][4],
    float* out, long long bg0,
    int tid, int lane, int wr, int wc, int tg, int tc)
{
    const int NS = (KSM == 2) ? 4 : 8;   // stages this layer
    float D[2][4][4];
#pragma unroll
    for (int rg = 0; rg < 2; rg++)
#pragma unroll
        for (int nt = 0; nt < 4; nt++)
#pragma unroll
            for (int j = 0; j < 4; j++) D[rg][nt][j] = 0.f;

    int buf = 0;
    for (int s = 0; s < NS; s++) {
        if (s + 1 < NS) fetch_stage(wf_sm + (buf ^ 1) * 32768, ci0 + 4 * (s + 1), tid);
        else if (!LAST) fetch_stage(wf_sm + (buf ^ 1) * 32768, nextci0, tid);
        compute_stage<KSM>(WFs + buf * 4096, AH, x0h, s, wr, wc, tg, lane, D);
        CP_WAIT0();
        __syncthreads();
        buf ^= 1;
    }

    // relu -> xk_s [r][k]
#pragma unroll
    for (int rg = 0; rg < 2; rg++) {
        int r0 = wr * 32 + rg * 16 + tg;
#pragma unroll
        for (int nt = 0; nt < 4; nt++) {
            int cb = wc * 32 + nt * 8 + tc * 2;
            *(float2*)&xk_s[r0 * 64 + cb] =
                make_float2(fmaxf(D[rg][nt][0], 0.f), fmaxf(D[rg][nt][1], 0.f));
            *(float2*)&xk_s[(r0 + 8) * 64 + cb] =
                make_float2(fmaxf(D[rg][nt][2], 0.f), fmaxf(D[rg][nt][3], 0.f));
        }
    }
    __syncthreads();

    // d-reduce -> out
    {
        int ob = tid >> 5, ok = (tid & 31) * 2;
        float s0 = 0.f, s1 = 0.f;
#pragma unroll
        for (int d = 0; d < 16; d++) {
            float2 v = *(const float2*)&xk_s[(ob * 16 + d) * 64 + ok];
            s0 += v.x; s1 += v.y;
        }
        *(float2*)&out[(bg0 + ob) * 192 + L * 64 + ok] = make_float2(s0, s1);
    }
    if (!LAST) {
        int c0 = tc * 2;
        build_A<4>(xk_s, AH, wr, tg, c0);
    }
    __syncthreads();
}

__global__ void __launch_bounds__(THREADS, 2)
cin_kernel(const float* __restrict__ emb,
           const float* __restrict__ W0,
           const float* __restrict__ W1,
           const float* __restrict__ W2,
           float* __restrict__ out)
{
    extern __shared__ char smem[];
    float*    x0_s = (float*)(smem + O_X0);     // fp32 staging, then...
    uint32_t* x0h  = (uint32_t*)(smem + O_X0);  // ...dup'd half2 [r][m]
    float* xk_s = (float*)(smem + O_XK);
    uint2* WFs  = (uint2*)(smem + O_WF);
    const uint32_t wf_sm = smem_u32(smem + O_WF);

    const int tid = threadIdx.x, lane = tid & 31, w = tid >> 5;
    const int wr = w & 3;         // row-warp: rows 32*wr .. 32*wr+31
    const int wc = w >> 2;        // col-warp: cols 32*wc .. 32*wc+31
    const int tg = lane >> 2, tc = lane & 3;
    const int c0 = tc * 2;
    const long long bg0 = (long long)blockIdx.x * TB;

    // load x0 fp32 (coalesced)
    {
        const float4* g = (const float4*)(emb + bg0 * 512);
        float4* sp = (float4*)x0_s;
#pragma unroll
        for (int i = 0; i < 4; i++) sp[tid + i * THREADS] = g[tid + i * THREADS];
    }
    // prefetch stage 0 (chunks 0..3)
    fetch_stage(wf_sm, 0, tid);
    __syncthreads();

    // xk_s[r][h] = x0[b][h][d]  (r = b*16+d, h < 32), and stage this
    // thread's 16 x0h entries in regs for the in-place transmute
    float v[16];
#pragma unroll
    for (int i = tid; i < 4096; i += THREADS) {
        int r = i >> 5, h = i & 31;
        xk_s[r * 64 + h] = x0_s[((r >> 4) << 9) + h * 16 + (r & 15)];
    }
#pragma unroll
    for (int i = 0; i < 16; i++) {
        int e = tid * 16 + i;            // e = r*32 + m
        int r = e >> 5, m = e & 31;
        v[i] = x0_s[((r >> 4) << 9) + m * 16 + (r & 15)];
    }
    __syncthreads();
    // x0h[r*32+m] = dup_h2(x0[b,m,d]) — overwrites the fp32 staging area
#pragma unroll
    for (int i = 0; i < 16; i++) {
        uint32_t d2 = pack_h2(v[i], v[i]);
        x0h[tid * 16 + i] = d2;
    }
    CP_WAIT0();
    __syncthreads();

    uint4 AH[2][4];
    build_A<2>(xk_s, AH, wr, tg, c0);

    layer<2, false>(0,  16, 0, x0h, xk_s, WFs, wf_sm, AH, out, bg0,
                    tid, lane, wr, wc, tg, tc);
    layer<4, false>(16, 48, 1, x0h, xk_s, WFs, wf_sm, AH, out, bg0,
                    tid, lane, wr, wc, tg, tc);
    layer<4, true >(48, 0,  2, x0h, xk_s, WFs, wf_sm, AH, out, bg0,
                    tid, lane, wr, wc, tg, tc);
}

extern "C" void kernel_launch(void* const* d_in, const int* in_sizes, int n_in,
                              void* d_out, int out_size)
{
    const float* emb = (const float*)d_in[0];
    const float* W0  = (const float*)d_in[1];
    const float* W1  = (const float*)d_in[2];
    const float* W2  = (const float*)d_in[3];
    float* out = (float*)d_out;

    prep_kernel<<<320, 256>>>(W0, W1, W2);
    cudaFuncSetAttribute(cin_kernel,
                         cudaFuncAttributeMaxDynamicSharedMemorySize, SM_TOTAL);
    cin_kernel<<<16384 / TB, THREADS, SM_TOTAL>>>(emb, W0, W1, W2, out);
}